// round 16
// baseline (speedup 1.0000x reference)
#include <cuda_runtime.h>
#include <cuda_fp16.h>
#include <math.h>
#include <stdint.h>

#define BATCH 2
#define SEQ   2048
#define EMB   512
#define HEADS 8
#define HDIM  64
#define MROWS 4096
#define KW    512    // everything single-term fp16, plain 512-col rows

// ---------------------------------------------------------------------------
// Scratch (device globals; allocation in kernel_launch is forbidden)
// ---------------------------------------------------------------------------
__device__ __align__(16) __half g_bA1[MROWS * KW];
__device__ __align__(16) __half g_bA2[MROWS * KW];
__device__ __align__(16) __half g_bA3[MROWS * KW];
__device__ __align__(16) __half g_bW [5 * EMB * KW];
__device__ __align__(16) __half g_Qb [MROWS * KW];
__device__ __align__(16) __half g_Kb [MROWS * KW];
__device__ __align__(16) __half g_Vb [MROWS * KW];
__device__ __align__(16) float  g_G  [MROWS * EMB];
__device__ __align__(16) __half g_bX2[MROWS * KW];
__device__ __align__(16) float  g_part[2 * MROWS * EMB];
__device__ __align__(16) float g_sin[SEQ * 32];
__device__ __align__(16) float g_cos[SEQ * 32];

// ---------------------------------------------------------------------------
// Host-side stream/event resources, created once at module load (host-side
// driver objects; no device-memory allocation inside kernel_launch).
// ---------------------------------------------------------------------------
struct HxStreams {
    cudaStream_t s2;
    cudaEvent_t e0, e1;
    HxStreams() {
        cudaStreamCreateWithFlags(&s2, cudaStreamNonBlocking);
        cudaEventCreateWithFlags(&e0, cudaEventDisableTiming);
        cudaEventCreateWithFlags(&e1, cudaEventDisableTiming);
    }
};
static HxStreams g_hs;

// ---------------------------------------------------------------------------
// Helpers
// ---------------------------------------------------------------------------
__device__ __forceinline__ uint32_t smem_u32(const void* p) {
    uint32_t a;
    asm("{ .reg .u64 t; cvta.to.shared.u64 t, %1; cvt.u32.u64 %0, t; }"
        : "=r"(a) : "l"(p));
    return a;
}

__device__ __forceinline__ void mma_f16(float* c, uint32_t a0, uint32_t a1,
                                        uint32_t a2, uint32_t a3,
                                        uint32_t b0, uint32_t b1) {
    asm volatile(
        "mma.sync.aligned.m16n8k16.row.col.f32.f16.f16.f32 "
        "{%0,%1,%2,%3}, {%4,%5,%6,%7}, {%8,%9}, {%0,%1,%2,%3};\n"
        : "+f"(c[0]), "+f"(c[1]), "+f"(c[2]), "+f"(c[3])
        : "r"(a0), "r"(a1), "r"(a2), "r"(a3), "r"(b0), "r"(b1));
}

__device__ __forceinline__ void ldsm4(uint32_t* r, uint32_t addr) {
    asm volatile("ldmatrix.sync.aligned.m8n8.x4.shared.b16 {%0,%1,%2,%3}, [%4];"
                 : "=r"(r[0]), "=r"(r[1]), "=r"(r[2]), "=r"(r[3]) : "r"(addr));
}
__device__ __forceinline__ void ldsm4t(uint32_t* r, uint32_t addr) {
    asm volatile("ldmatrix.sync.aligned.m8n8.x4.trans.shared.b16 {%0,%1,%2,%3}, [%4];"
                 : "=r"(r[0]), "=r"(r[1]), "=r"(r[2]), "=r"(r[3]) : "r"(addr));
}

#define CP16(dst, src) \
    asm volatile("cp.async.cg.shared.global [%0], [%1], 16;" \
                 :: "r"((uint32_t)(dst)), "l"(src))
#define CP_COMMIT() asm volatile("cp.async.commit_group;" ::: "memory")
#define CP_WAIT0()  asm volatile("cp.async.wait_group 0;" ::: "memory")

__device__ __forceinline__ uint32_t pk2h(__half a, __half b) {
    uint16_t lo = *(uint16_t*)&a, hi = *(uint16_t*)&b;
    return (uint32_t)lo | ((uint32_t)hi << 16);
}

// ---------------------------------------------------------------------------
// prep: fp32 -> fp16 conversions (3 activations + 5 weights) + rotary tables.
// Flattened exact grid: 6144 act blocks + 1280 weight blocks + 256 rope.
// ---------------------------------------------------------------------------
__device__ __forceinline__ void conv4(const float* __restrict__ src,
                                      __half* __restrict__ dst, int idx) {
    int row = idx >> 7, c = (idx & 127) << 2;
    float4 v = *(const float4*)(src + (size_t)row * EMB + c);
    __half h[4];
    h[0] = __float2half_rn(v.x); h[1] = __float2half_rn(v.y);
    h[2] = __float2half_rn(v.z); h[3] = __float2half_rn(v.w);
    uint2 hp;
    hp.x = pk2h(h[0], h[1]); hp.y = pk2h(h[2], h[3]);
    *(uint2*)(dst + (size_t)row * KW + c) = hp;
}

__global__ void __launch_bounds__(256)
prep_k(const float* __restrict__ q0, const float* __restrict__ k0,
       const float* __restrict__ v0,
       const float* __restrict__ w0, const float* __restrict__ w1,
       const float* __restrict__ w2, const float* __restrict__ w3,
       const float* __restrict__ w4,
       __half* __restrict__ a0, __half* __restrict__ a1,
       __half* __restrict__ a2, __half* __restrict__ wd,
       float* __restrict__ st, float* __restrict__ ct) {
    const int bid = blockIdx.x;
    const int tid = threadIdx.x;
    if (bid < 6144) {                       // activations: 3 x 2048 blocks
        const int y = bid >> 11;            // /2048
        const int idx = ((bid & 2047) << 8) + tid;
        const float* s = (y == 0) ? q0 : (y == 1) ? k0 : v0;
        __half* d = (y == 0) ? a0 : (y == 1) ? a1 : a2;
        conv4(s, d, idx);
    } else if (bid < 7424) {                // weights: 5 x 256 blocks
        const int r = bid - 6144;
        const int w = r >> 8;               // /256
        const int idx = ((r & 255) << 8) + tid;
        const float* s;
        switch (w) {
            case 0: s = w0; break;
            case 1: s = w1; break;
            case 2: s = w2; break;
            case 3: s = w3; break;
            default: s = w4; break;
        }
        conv4(s, wd + (size_t)w * EMB * KW, idx);
    } else {                                // rope: 256 blocks
        const int idx = ((bid - 7424) << 8) + tid;
        int n = idx >> 5, p = idx & 31;
        float theta = powf(10000.f, -(float)p * (1.0f / 31.0f));
        float sv, cv;
        sincosf((float)n * theta, &sv, &cv);
        st[idx] = sv;
        ct[idx] = cv;
    }
}

// ---------------------------------------------------------------------------
// Projection GEMM (merged, single-term fp16): CTA 128x128, warp 32x64.
// phase 0: z=0 Q(rotary), z=1 K(rotary*.125), z=2 V        (Q/K/V only)
// phase 1: output projection (fp32 out)
// phase 2: G gate projection (silu, fp32 out) — separate stream
// ---------------------------------------------------------------------------
#define PJ_P   144
#define PJ_BUF 18432             // 128 rows * 144 B
#define PJ_SMEM (4 * PJ_BUF)     // 73728
#define PJ_CHUNKS 8

__global__ void __launch_bounds__(256, 2)
proj_all(const __half* __restrict__ bA1, const __half* __restrict__ bA2,
         const __half* __restrict__ bA3, const __half* __restrict__ bX2,
         const __half* __restrict__ bW,
         const float* __restrict__ bq, const float* __restrict__ bk,
         const float* __restrict__ bv, const float* __restrict__ bg,
         const float* __restrict__ bo,
         __half* __restrict__ Qb, __half* __restrict__ Kb,
         __half* __restrict__ Vb, float* __restrict__ Gf,
         float* __restrict__ outp, int phase)
{
    extern __shared__ char sm[];
    const uint32_t smb = smem_u32(sm);
    const int tid = threadIdx.x;
    const int lane = tid & 31, wid = tid >> 5;
    const int g = lane >> 2, tig = lane & 3;
    const int wm = wid >> 1, wn = wid & 1;
    const int mBase = blockIdx.y * 128, nBase = blockIdx.x * 128;
    const int z = blockIdx.z;

    const __half* A;
    const float* bias;
    int mode;
    void* Cout;
    const size_t wOff = (size_t)EMB * KW;
    const __half* W;
    if (phase == 0) {
        if (z == 0)      { A = bA1; W = bW;            bias = bq; mode = 2; Cout = Qb; }
        else if (z == 1) { A = bA2; W = bW + 1 * wOff; bias = bk; mode = 3; Cout = Kb; }
        else             { A = bA3; W = bW + 2 * wOff; bias = bv; mode = 4; Cout = Vb; }
    } else if (phase == 2) {
        A = bA1; W = bW + 3 * wOff; bias = bg; mode = 1; Cout = Gf;
    } else {
        A = bX2; W = bW + 4 * wOff; bias = bo; mode = 0; Cout = outp;
    }

    const int aRow   = lane & 15;
    const int aOff16 = (lane >> 4) * 16;
    const int bRow   = (lane & 7) + ((lane >> 4) << 3);
    const int bOff16 = ((lane >> 3) & 1) * 16;

    float acc[2][8][4];
#pragma unroll
    for (int a = 0; a < 2; a++)
#pragma unroll
        for (int b = 0; b < 8; b++)
#pragma unroll
            for (int c = 0; c < 4; c++) acc[a][b][c] = 0.f;

    const int crow = tid >> 1;
    const int csel = tid & 1;
    const __half* Arow = A + (size_t)(mBase + crow) * KW;
    const __half* Wrow = W + (size_t)(nBase + crow) * KW;

#define LOADC(c) do {                                                          \
    const int _b = (c) & 1;                                                    \
    const uint32_t _ad = smb + _b * PJ_BUF + crow * PJ_P + csel * 64;          \
    const __half* _as = Arow + (c) * 64 + csel * 32;                           \
    _Pragma("unroll")                                                          \
    for (int _i = 0; _i < 4; _i++) CP16(_ad + _i * 16, _as + _i * 8);          \
    const uint32_t _wd = smb + 2 * PJ_BUF + _b * PJ_BUF + crow * PJ_P + csel * 64; \
    const __half* _ws = Wrow + (c) * 64 + csel * 32;                           \
    _Pragma("unroll")                                                          \
    for (int _i = 0; _i < 4; _i++) CP16(_wd + _i * 16, _ws + _i * 8);          \
} while (0)

    LOADC(0);
    CP_COMMIT();

    for (int c = 0; c < PJ_CHUNKS; c++) {
        CP_WAIT0();
        __syncthreads();
        if (c + 1 < PJ_CHUNKS) {
            LOADC(c + 1);
            CP_COMMIT();
        }
        const uint32_t aS = smb + (c & 1) * PJ_BUF;
        const uint32_t wS = smb + 2 * PJ_BUF + (c & 1) * PJ_BUF;
#pragma unroll
        for (int ks = 0; ks < 4; ks++) {
            uint32_t av[2][4];
#pragma unroll
            for (int mt = 0; mt < 2; mt++)
                ldsm4(av[mt], aS + (wm * 32 + mt * 16 + aRow) * PJ_P
                              + ks * 32 + aOff16);
            uint32_t bq4[4][4];
#pragma unroll
            for (int nt2 = 0; nt2 < 4; nt2++)
                ldsm4(bq4[nt2], wS + (wn * 64 + nt2 * 16 + bRow) * PJ_P
                                + ks * 32 + bOff16);
#pragma unroll
            for (int nt2 = 0; nt2 < 4; nt2++) {
#pragma unroll
                for (int mt = 0; mt < 2; mt++) {
                    mma_f16(acc[mt][nt2 * 2 + 0],
                            av[mt][0], av[mt][1], av[mt][2], av[mt][3],
                            bq4[nt2][0], bq4[nt2][1]);
                    mma_f16(acc[mt][nt2 * 2 + 1],
                            av[mt][0], av[mt][1], av[mt][2], av[mt][3],
                            bq4[nt2][2], bq4[nt2][3]);
                }
            }
        }
    }
#undef LOADC

    // epilogue
#pragma unroll
    for (int mt = 0; mt < 2; mt++) {
#pragma unroll
        for (int half = 0; half < 2; half++) {
            const int row = mBase + wm * 32 + mt * 16 + g + half * 8;
            const int nseq = row & (SEQ - 1);
#pragma unroll
            for (int nt = 0; nt < 8; nt++) {
                const int col = nBase + wn * 64 + nt * 8 + tig * 2;
                float v0 = acc[mt][nt][half * 2 + 0] + __ldg(bias + col);
                float v1 = acc[mt][nt][half * 2 + 1] + __ldg(bias + col + 1);
                if (mode == 0) {
                    *(float2*)((float*)Cout + (size_t)row * EMB + col) =
                        make_float2(v0, v1);
                } else if (mode == 1) {
                    v0 = v0 / (1.f + expf(-v0));
                    v1 = v1 / (1.f + expf(-v1));
                    *(float2*)((float*)Cout + (size_t)row * EMB + col) =
                        make_float2(v0, v1);
                } else {
                    float x = v0, y = v1;
                    if (mode == 2 || mode == 3) {
                        const int d = col & 63, p = d >> 1;
                        const float sv = g_sin[nseq * 32 + p];
                        const float cv = g_cos[nseq * 32 + p];
                        x = v0 * cv - v1 * sv;
                        y = v1 * cv + v0 * sv;
                        if (mode == 3) { x *= 0.125f; y *= 0.125f; }
                    }
                    __half* C = (__half*)Cout;
                    *(uint32_t*)(C + (size_t)row * KW + col) =
                        pk2h(__float2half_rn(x), __float2half_rn(y));
                }
            }
        }
    }
}

// ---------------------------------------------------------------------------
// Retention, single-term fp16, split-K load balance, double-buffered K/V via
// cp.async (one barrier per s-tile). grid (32, 16): x -> (rb, shalf).
// ---------------------------------------------------------------------------
#define RT_P    144
#define RT_QS   0
#define RT_KV   18432
#define RT_PAIR 36864            // one (K,V) buffer pair
#define RT_TAB  92160
#define RT_SMEM 93184

__global__ void __launch_bounds__(256, 2)
ret_k(const __half* __restrict__ Qb, const __half* __restrict__ Kb,
      const __half* __restrict__ Vb, float* __restrict__ P)
{
    extern __shared__ char sm[];
    const uint32_t smb = smem_u32(sm);
    float* tab = (float*)(sm + RT_TAB);
    const int tid = threadIdx.x;
    const int lane = tid & 31, wid = tid >> 5;
    const int g = lane >> 2, tig = lane & 3;
    const int rb = 15 - ((int)blockIdx.x >> 1);
    const int shalf = blockIdx.x & 1;
    const int rowBase = rb * 128;
    const int bh = blockIdx.y;
    const int b = bh >> 3, h = bh & 7;

    const int n0 = (rb + 2) >> 1;
    const int s0 = shalf ? n0 : 0;
    const int s1 = shalf ? (rb + 1) : n0;

    const int aRow   = lane & 15;
    const int aOff16 = (lane >> 4) * 16;
    const int bRow   = (lane & 7) + ((lane >> 4) << 3);
    const int bOff16 = ((lane >> 3) & 1) * 16;
    const int vRow   = (lane & 7) + (((lane >> 3) & 1) << 3);
    const int vCol16 = ((lane >> 4) & 1) * 16;

    const double la = -3.4657359027997265;   // log(1/32)
    const double lb = -6.2383246250395075;   // log(1/512)
    const float gamma = (float)(1.0 - exp(la + (lb - la) * ((double)h / 7.0)));
    const float lg2g = log2f(gamma);
    if (tid < 256) tab[tid] = exp2f(lg2g * (float)(tid - 128));

    const int crow = tid >> 1;
    const int csel = tid & 1;
    const __half* Kbase = Kb + (size_t)(b * SEQ) * KW + h * 64
                          + (size_t)crow * KW + csel * 32;
    const __half* Vbase = Vb + (size_t)(b * SEQ) * KW + h * 64
                          + (size_t)crow * KW + csel * 32;
    const uint32_t stDst = smb + RT_KV + crow * RT_P + csel * 64;

#define LOADKV(sT, buf) do {                                                  \
    const size_t _go = (size_t)(sT) * 128 * KW;                               \
    const uint32_t _kd = stDst + (uint32_t)(buf) * RT_PAIR;                   \
    const __half* _ks = Kbase + _go;                                          \
    const __half* _vs = Vbase + _go;                                          \
    _Pragma("unroll")                                                         \
    for (int _i = 0; _i < 4; _i++) CP16(_kd + _i * 16, _ks + _i * 8);         \
    _Pragma("unroll")                                                         \
    for (int _i = 0; _i < 4; _i++) CP16(_kd + 18432 + _i * 16, _vs + _i * 8); \
} while (0)

    // Q tile: 128 rows x 64 fp16
    if (s0 < s1) {
        const __half* qs = Qb + (size_t)(b * SEQ + rowBase) * KW + h * 64;
        for (int e = tid; e < 128 * 8; e += 256) {
            int r = e >> 3, q = e & 7;
            *(uint4*)(sm + RT_QS + r * RT_P + q * 16) =
                *(const uint4*)(qs + (size_t)r * KW + q * 8);
        }
        LOADKV(s0, 0);
        CP_COMMIT();
    }

    float sacc[8][4];
#pragma unroll
    for (int i = 0; i < 8; i++)
#pragma unroll
        for (int j = 0; j < 4; j++) sacc[i][j] = 0.f;

    const uint32_t qAddr = smb + RT_QS + (wid * 16 + aRow) * RT_P + aOff16;

    for (int sT = s0; sT < s1; sT++) {
        CP_WAIT0();
        __syncthreads();
        if (sT + 1 < s1) {
            LOADKV(sT + 1, (sT + 1 - s0) & 1);
            CP_COMMIT();
        }
        const uint32_t kvB = smb + RT_KV + (uint32_t)((sT - s0) & 1) * RT_PAIR;
        const uint32_t vAddrBase = kvB + 18432 + vRow * RT_P + vCol16;

        const int colBase = sT * 128;
        const float basefac = exp2f(lg2g * (float)(rowBase - colBase));
        const bool diag = (sT == rb);
        const int li0 = wid * 16 + g;

#pragma unroll
        for (int qt = 0; qt < 4; qt++) {
            float qk[4][4];
#pragma unroll
            for (int i = 0; i < 4; i++)
#pragma unroll
                for (int j = 0; j < 4; j++) qk[i][j] = 0.f;

#pragma unroll
            for (int ks = 0; ks < 4; ks++) {
                uint32_t aH[4];
                ldsm4(aH, qAddr + ks * 32);
#pragma unroll
                for (int nt2 = 0; nt2 < 2; nt2++) {
                    uint32_t bvv[4];
                    ldsm4(bvv, kvB + (qt * 32 + nt2 * 16 + bRow) * RT_P
                               + ks * 32 + bOff16);
                    mma_f16(qk[nt2 * 2 + 0], aH[0], aH[1], aH[2], aH[3], bvv[0], bvv[1]);
                    mma_f16(qk[nt2 * 2 + 1], aH[0], aH[1], aH[2], aH[3], bvv[2], bvv[3]);
                }
            }

            uint32_t sh01[4], sh23[4];
#pragma unroll
            for (int nt = 0; nt < 4; nt++) {
                const int lj = qt * 32 + nt * 8 + tig * 2;
                const int d00 = li0 - lj,     d01 = d00 - 1;
                const int d10 = li0 + 8 - lj, d11 = d10 - 1;
                float w00 = basefac * tab[d00 + 128];
                float w01 = basefac * tab[d01 + 128];
                float w10 = basefac * tab[d10 + 128];
                float w11 = basefac * tab[d11 + 128];
                if (diag && d00 < 0) w00 = 0.f;
                if (diag && d01 < 0) w01 = 0.f;
                if (diag && d10 < 0) w10 = 0.f;
                if (diag && d11 < 0) w11 = 0.f;
                sh01[nt] = pk2h(__float2half_rn(qk[nt][0] * w00),
                                __float2half_rn(qk[nt][1] * w01));
                sh23[nt] = pk2h(__float2half_rn(qk[nt][2] * w10),
                                __float2half_rn(qk[nt][3] * w11));
            }

#pragma unroll
            for (int ksl = 0; ksl < 2; ksl++) {
                uint32_t ah[4] = {sh01[2 * ksl], sh23[2 * ksl],
                                  sh01[2 * ksl + 1], sh23[2 * ksl + 1]};
                const uint32_t vRowAddr = vAddrBase + (qt * 2 + ksl) * 16 * RT_P;
#pragma unroll
                for (int dt = 0; dt < 4; dt++) {
                    uint32_t bhv[4];
                    ldsm4t(bhv, vRowAddr + dt * 32);
                    mma_f16(sacc[dt * 2 + 0], ah[0], ah[1], ah[2], ah[3], bhv[0], bhv[1]);
                    mma_f16(sacc[dt * 2 + 1], ah[0], ah[1], ah[2], ah[3], bhv[2], bhv[3]);
                }
            }
        }
    }
#undef LOADKV

    float* P0 = P + (size_t)shalf * (MROWS * EMB);
    const int mrowA = b * SEQ + rowBase + wid * 16 + g;
    const int mrowB = mrowA + 8;
#pragma unroll
    for (int nt = 0; nt < 8; nt++) {
        const int d = nt * 8 + tig * 2;
        *(float2*)(P0 + (size_t)mrowA * EMB + h * 64 + d) =
            make_float2(sacc[nt][0], sacc[nt][1]);
        *(float2*)(P0 + (size_t)mrowB * EMB + h * 64 + d) =
            make_float2(sacc[nt][2], sacc[nt][3]);
    }
}

// ---------------------------------------------------------------------------
// Reduce partials + GroupNorm + gate + fp16 store. One warp per (row,h).
// ---------------------------------------------------------------------------
__global__ void __launch_bounds__(256)
ret_fin(const float* __restrict__ P, const float* __restrict__ G,
        __half* __restrict__ X2)
{
    const int w = blockIdx.x * 8 + (threadIdx.x >> 5);
    const int lane = threadIdx.x & 31;
    const int mrow = w >> 3, h = w & 7;
    const size_t base = (size_t)mrow * EMB + h * 64 + lane * 2;

    const float2 a = *(const float2*)(P + base);
    const float2 b2 = *(const float2*)(P + (size_t)MROWS * EMB + base);
    const float x0 = a.x + b2.x;
    const float x1 = a.y + b2.y;

    float s1 = x0 + x1;
    float s2 = x0 * x0 + x1 * x1;
#pragma unroll
    for (int m = 16; m >= 1; m >>= 1) {
        s1 += __shfl_xor_sync(0xffffffffu, s1, m);
        s2 += __shfl_xor_sync(0xffffffffu, s2, m);
    }
    const float mean = s1 * (1.f / 64.f);
    float var = fmaxf(s2 * (1.f / 64.f) - mean * mean, 0.f);
    const float inv = rsqrtf(var + 1e-6f);

    const float2 gg = *(const float2*)(G + base);
    const float y0 = (x0 - mean) * inv * gg.x;
    const float y1 = (x1 - mean) * inv * gg.y;

    *(uint32_t*)(X2 + (size_t)mrow * KW + h * 64 + lane * 2) =
        pk2h(__float2half_rn(y0), __float2half_rn(y1));
}

// ---------------------------------------------------------------------------
// Launch: G-projection forked onto a second stream, overlapping Q/K/V proj
// and ret_k; joined before ret_fin.
// ---------------------------------------------------------------------------
extern "C" void kernel_launch(void* const* d_in, const int* in_sizes, int n_in,
                              void* d_out, int out_size)
{
    (void)in_sizes; (void)n_in; (void)out_size;
    const float* query = (const float*)d_in[0];
    const float* kin   = (const float*)d_in[1];
    const float* vin   = (const float*)d_in[2];
    const float* Wq = (const float*)d_in[3];  const float* bq = (const float*)d_in[4];
    const float* Wk = (const float*)d_in[5];  const float* bk = (const float*)d_in[6];
    const float* Wv = (const float*)d_in[7];  const float* bv = (const float*)d_in[8];
    const float* Wg = (const float*)d_in[9];  const float* bg = (const float*)d_in[10];
    const float* Wo = (const float*)d_in[11]; const float* bo = (const float*)d_in[12];
    float* out = (float*)d_out;

    float *Gf, *sinp, *cosp, *Pp;
    __half *bA1, *bA2, *bA3, *bW, *Qb, *Kb, *Vb, *bX2;
    cudaGetSymbolAddress((void**)&bA1, g_bA1);
    cudaGetSymbolAddress((void**)&bA2, g_bA2);
    cudaGetSymbolAddress((void**)&bA3, g_bA3);
    cudaGetSymbolAddress((void**)&bW,  g_bW);
    cudaGetSymbolAddress((void**)&Qb,  g_Qb);
    cudaGetSymbolAddress((void**)&Kb,  g_Kb);
    cudaGetSymbolAddress((void**)&Vb,  g_Vb);
    cudaGetSymbolAddress((void**)&Gf,  g_G);
    cudaGetSymbolAddress((void**)&bX2, g_bX2);
    cudaGetSymbolAddress((void**)&Pp,  g_part);
    cudaGetSymbolAddress((void**)&sinp, g_sin);
    cudaGetSymbolAddress((void**)&cosp, g_cos);

    cudaFuncSetAttribute(proj_all, cudaFuncAttributeMaxDynamicSharedMemorySize, PJ_SMEM);
    cudaFuncSetAttribute(ret_k, cudaFuncAttributeMaxDynamicSharedMemorySize, RT_SMEM);

    prep_k<<<7680, 256>>>(query, kin, vin, Wq, Wk, Wv, Wg, Wo,
                          bA1, bA2, bA3, bW, sinp, cosp);

    // fork: G projection on side stream (depends only on prep)
    cudaEventRecord(g_hs.e0, 0);
    cudaStreamWaitEvent(g_hs.s2, g_hs.e0, 0);
    dim3 pgG(EMB / 128, MROWS / 128, 1);
    proj_all<<<pgG, 256, PJ_SMEM, g_hs.s2>>>(bA1, bA2, bA3, bX2, bW,
                                             bq, bk, bv, bg, bo,
                                             Qb, Kb, Vb, Gf, out, 2);
    cudaEventRecord(g_hs.e1, g_hs.s2);

    // main: Q/K/V projections, then retention
    dim3 pg3(EMB / 128, MROWS / 128, 3);
    proj_all<<<pg3, 256, PJ_SMEM>>>(bA1, bA2, bA3, bX2, bW,
                                    bq, bk, bv, bg, bo,
                                    Qb, Kb, Vb, Gf, out, 0);

    dim3 rg(32, BATCH * HEADS);
    ret_k<<<rg, 256, RT_SMEM>>>(Qb, Kb, Vb, Pp);

    // join: ret_fin needs Gf from the side stream
    cudaStreamWaitEvent(0, g_hs.e1, 0);
    ret_fin<<<MROWS, 256>>>(Pp, Gf, bX2);

    dim3 pg1(EMB / 128, MROWS / 128, 1);
    proj_all<<<pg1, 256, PJ_SMEM>>>(bA1, bA2, bA3, bX2, bW,
                                    bq, bk, bv, bg, bo,
                                    Qb, Kb, Vb, Gf, out, 1);
}